// round 5
// baseline (speedup 1.0000x reference)
#include <cuda_runtime.h>
#include <cuda_bf16.h>
#include <cstdint>

// rnn_two: out = h2_last @ Wo for two stacked LINEAR SimpleRNNs.
// Linearity => out = sum_t x_t @ A_t with A_t = W1 @ S(15-t) @ Wo,
// S(m) = sum_{j=0..m} U1^j W2 U2^(m-j), via log-depth doubling.
// ALL matmuls (precompute + main) run on mma.sync bf16 hi/lo split
// (3 products, fp32 accumulate). Precompute loads fragments directly from
// gmem fp32 (L2-resident) — no smem, no ldmatrix.

#define NN 256
#define TT 16
#define MSZ (NN * NN)
#define BB 8192
#define KTOT (TT * NN)   // 4096

__device__ __align__(16) float g_P1[9][MSZ];
__device__ __align__(16) float g_P2[9][MSZ];
__device__ __align__(16) float g_S[TT][MSZ];
__device__ __align__(16) float g_TMP[TT][MSZ];
// Acat transposed + bf16-split: g_Bhi/lo[n][kglobal], kglobal = t*256 + j
__device__ __align__(16) __nv_bfloat16 g_Bhi[NN * KTOT];
__device__ __align__(16) __nv_bfloat16 g_Blo[NN * KTOT];

// ---------------------------------------------------------------------------
// Common helpers
// ---------------------------------------------------------------------------
__device__ __forceinline__ uint32_t s2u(const void* p) {
    uint32_t a;
    asm("{ .reg .u64 t; cvta.to.shared.u64 t, %1; cvt.u32.u64 %0, t; }"
        : "=r"(a) : "l"(p));
    return a;
}
__device__ __forceinline__ uint32_t sw128(uint32_t b) {
    return b ^ ((b >> 3) & 0x70);
}
__device__ __forceinline__ void cp16(uint32_t dst, const void* src) {
    asm volatile("cp.async.cg.shared.global [%0], [%1], 16;"
                 :: "r"(dst), "l"(src));
}
__device__ __forceinline__ void cp_commit() {
    asm volatile("cp.async.commit_group;");
}
__device__ __forceinline__ void cp_wait1() {
    asm volatile("cp.async.wait_group 1;" ::: "memory");
}
__device__ __forceinline__ void ldsm4(uint32_t r[4], uint32_t addr) {
    asm volatile("ldmatrix.sync.aligned.m8n8.x4.shared.b16 {%0,%1,%2,%3}, [%4];"
                 : "=r"(r[0]), "=r"(r[1]), "=r"(r[2]), "=r"(r[3]) : "r"(addr));
}
__device__ __forceinline__ void mma16816(float c[4], const uint32_t a[4],
                                         uint32_t b0, uint32_t b1) {
    asm volatile(
        "mma.sync.aligned.m16n8k16.row.col.f32.bf16.bf16.f32 "
        "{%0,%1,%2,%3}, {%4,%5,%6,%7}, {%8,%9}, {%0,%1,%2,%3};"
        : "+f"(c[0]), "+f"(c[1]), "+f"(c[2]), "+f"(c[3])
        : "r"(a[0]), "r"(a[1]), "r"(a[2]), "r"(a[3]), "r"(b0), "r"(b1));
}
__device__ __forceinline__ void splitf2(float2 v, uint32_t& hi, uint32_t& lo) {
    __nv_bfloat162 h = __float22bfloat162_rn(v);
    float2 hf = __bfloat1622float2(h);
    __nv_bfloat162 L = __float22bfloat162_rn(make_float2(v.x - hf.x, v.y - hf.y));
    hi = *reinterpret_cast<uint32_t*>(&h);
    lo = *reinterpret_cast<uint32_t*>(&L);
}

// ---------------------------------------------------------------------------
// Tensor-core 256x256x256 matmul, fragments straight from gmem fp32.
// Warp computes a 32(m) x 64(n) patch: acc[2][8][4]. rowM/colN absolute.
// ---------------------------------------------------------------------------
__device__ __forceinline__ void tc_mm_op(
    float* acc,  // [2*8*4]
    const float* __restrict__ A, const float* __restrict__ B,
    int rowM, int colN, int lane)
{
    const int g = lane >> 2, t = lane & 3;
    for (int k16 = 0; k16 < 16; ++k16) {
        const int k0 = k16 * 16;
        uint32_t ahi[2][4], alo[2][4];
#pragma unroll
        for (int mt = 0; mt < 2; ++mt) {
            const float* p = A + (size_t)(rowM + mt * 16 + g) * NN + k0 + 2 * t;
            float2 v0 = *(const float2*)p;
            float2 v1 = *(const float2*)(p + 8 * NN);
            float2 v2 = *(const float2*)(p + 8);
            float2 v3 = *(const float2*)(p + 8 * NN + 8);
            splitf2(v0, ahi[mt][0], alo[mt][0]);
            splitf2(v1, ahi[mt][1], alo[mt][1]);
            splitf2(v2, ahi[mt][2], alo[mt][2]);
            splitf2(v3, ahi[mt][3], alo[mt][3]);
        }
#pragma unroll
        for (int jp = 0; jp < 8; ++jp) {
            const float* q = B + (size_t)(k0 + 2 * t) * NN + colN + jp * 8 + g;
            float x0 = q[0],      x1 = q[NN];
            float x2 = q[8 * NN], x3 = q[9 * NN];
            uint32_t bh0, bl0, bh1, bl1;
            splitf2(make_float2(x0, x1), bh0, bl0);
            splitf2(make_float2(x2, x3), bh1, bl1);
#pragma unroll
            for (int mt = 0; mt < 2; ++mt) {
                float* c = acc + (mt * 8 + jp) * 4;
                mma16816(c, ahi[mt], bh0, bh1);
                mma16816(c, ahi[mt], bl0, bl1);
                mma16816(c, alo[mt], bh0, bh1);
            }
        }
    }
}

__device__ __forceinline__ void tc_store(
    const float* acc, float* __restrict__ C, int rowM, int colN, int lane)
{
    const int g = lane >> 2, t = lane & 3;
#pragma unroll
    for (int mt = 0; mt < 2; ++mt)
#pragma unroll
        for (int jp = 0; jp < 8; ++jp) {
            const float* c = acc + (mt * 8 + jp) * 4;
            int r = rowM + mt * 16 + g, col = colN + jp * 8 + 2 * t;
            *(float2*)&C[(size_t)r * NN + col] = make_float2(c[0], c[1]);
            *(float2*)&C[(size_t)(r + 8) * NN + col] = make_float2(c[2], c[3]);
        }
}

// ---------------------------------------------------------------------------
// Precompute kernels (tensor-core)
// ---------------------------------------------------------------------------
__global__ void k_init(const float* __restrict__ U1,
                       const float* __restrict__ U2,
                       const float* __restrict__ W2)
{
    int i = blockIdx.x * blockDim.x + threadIdx.x;
    g_P1[1][i] = U1[i];
    g_P2[1][i] = U2[i];
    g_S[0][i]  = W2[i];
}

__global__ void __launch_bounds__(256) k_stage_tc(int M)
{
    const int e_pow = min(M, 8 - M);
    const int job = blockIdx.y;
    const int tile = blockIdx.x;
    const int rowBase = (tile >> 1) * 128, colBase = (tile & 1) * 128;
    const int w = threadIdx.x >> 5, lane = threadIdx.x & 31;
    const int rowM = rowBase + (w >> 1) * 32;
    const int colN = colBase + (w & 1) * 64;

    const float *A0, *B0, *A1 = nullptr, *B1 = nullptr;
    float* C;
    if (job < e_pow) {
        int j = job + 1;
        A0 = g_P1[M]; B0 = g_P1[j]; C = g_P1[M + j];
    } else if (job < 2 * e_pow) {
        int j = job - e_pow + 1;
        A0 = g_P2[M]; B0 = g_P2[j]; C = g_P2[M + j];
    } else {
        int m = M + (job - 2 * e_pow);
        A0 = g_S[M - 1]; B0 = g_P2[m - M + 1];
        A1 = g_P1[M];    B1 = g_S[m - M];
        C = g_S[m];
    }

    float acc[2 * 8 * 4] = {};
    tc_mm_op(acc, A0, B0, rowM, colN, lane);
    if (A1) tc_mm_op(acc, A1, B1, rowM, colN, lane);
    tc_store(acc, C, rowM, colN, lane);
}

__global__ void __launch_bounds__(256) k_tmp_tc(const float* __restrict__ W1)
{
    const int m = blockIdx.y;
    const int tile = blockIdx.x;
    const int rowBase = (tile >> 1) * 128, colBase = (tile & 1) * 128;
    const int w = threadIdx.x >> 5, lane = threadIdx.x & 31;
    const int rowM = rowBase + (w >> 1) * 32;
    const int colN = colBase + (w & 1) * 64;

    float acc[2 * 8 * 4] = {};
    tc_mm_op(acc, W1, g_S[m], rowM, colN, lane);
    tc_store(acc, g_TMP[m], rowM, colN, lane);
}

// A_t = TMP[15-t] @ Wo; emit transposed + bf16-split via smem transpose.
__global__ void __launch_bounds__(256) k_afinal_tc(const float* __restrict__ Wo)
{
    extern __shared__ float cs[];  // [128][132]
    const int tIdx = blockIdx.y;
    const int tile = blockIdx.x;
    const int rowBase = (tile >> 1) * 128, colBase = (tile & 1) * 128;
    const int w = threadIdx.x >> 5, lane = threadIdx.x & 31;
    const int rowM = rowBase + (w >> 1) * 32;
    const int colN = colBase + (w & 1) * 64;
    const int g = lane >> 2, t = lane & 3;

    float acc[2 * 8 * 4] = {};
    tc_mm_op(acc, g_TMP[15 - tIdx], Wo, rowM, colN, lane);

    // stage tile into smem (local coords), padded stride 132
#pragma unroll
    for (int mt = 0; mt < 2; ++mt)
#pragma unroll
        for (int jp = 0; jp < 8; ++jp) {
            const float* c = acc + (mt * 8 + jp) * 4;
            int lr = (rowM - rowBase) + mt * 16 + g;
            int lc = (colN - colBase) + jp * 8 + 2 * t;
            cs[lr * 132 + lc] = c[0];
            cs[lr * 132 + lc + 1] = c[1];
            cs[(lr + 8) * 132 + lc] = c[2];
            cs[(lr + 8) * 132 + lc + 1] = c[3];
        }
    __syncthreads();

    // write split/transposed: g_Bhi[n][kglobal], 8B coalesced along k
    for (int j = threadIdx.x; j < 128 * 32; j += 256) {
        int n = j >> 5, m4 = j & 31;
        int kg = tIdx * NN + rowBase + m4 * 4;
        __nv_bfloat16 h[4], l[4];
#pragma unroll
        for (int r = 0; r < 4; ++r) {
            float v = cs[(m4 * 4 + r) * 132 + n];
            h[r] = __float2bfloat16_rn(v);
            l[r] = __float2bfloat16_rn(v - __bfloat162float(h[r]));
        }
        *(uint64_t*)&g_Bhi[(size_t)(colBase + n) * KTOT + kg] = *(uint64_t*)h;
        *(uint64_t*)&g_Blo[(size_t)(colBase + n) * KTOT + kg] = *(uint64_t*)l;
    }
}

// ---------------------------------------------------------------------------
// Main GEMM on mma.sync: out[8192,256] = X @ Acat.
// CTA 128x128, 8 warps; B via cp.async double buffer + ldmatrix;
// A fragments from gmem with 1-step register prefetch.
// ---------------------------------------------------------------------------
#define BM 128
#define BN 128
#define BKC 64
#define NCHUNK (KTOT / BKC)
#define BUFB 32768
#define GEMM_SMEM (2 * BUFB)

__global__ void __launch_bounds__(256)
k_gemm_mma(const float* __restrict__ X, float* __restrict__ out)
{
    extern __shared__ char smem[];
    const uint32_t sb = s2u(smem);
    const int tid = threadIdx.x;
    const int w = tid >> 5, l = tid & 31;
    const int rowBase = blockIdx.x * BM;
    const int colBase = blockIdx.y * BN;

    auto loadB = [&](int c, int b) {
        const uint32_t dhi = sb + b * BUFB;
        const uint32_t dlo = dhi + 16384;
#pragma unroll
        for (int p = 0; p < 4; ++p) {
            int id = tid + p * 256;
            int n = id >> 3, cc = id & 7;
            uint32_t off = sw128((uint32_t)(n * 128 + cc * 16));
            size_t gidx = (size_t)(colBase + n) * KTOT + c * BKC + cc * 8;
            cp16(dhi + off, &g_Bhi[gidx]);
            cp16(dlo + off, &g_Blo[gidx]);
        }
    };

    loadB(0, 0);
    cp_commit();

    const float* p0 = X + (size_t)(rowBase + w * 16 + (l >> 2)) * KTOT + (l & 3) * 2;
    const float* p1 = p0 + (size_t)8 * KTOT;

    float2 aN0 = *(const float2*)(p0);
    float2 aN1 = *(const float2*)(p1);
    float2 aN2 = *(const float2*)(p0 + 8);
    float2 aN3 = *(const float2*)(p1 + 8);

    float acc[16][4];
#pragma unroll
    for (int j = 0; j < 16; ++j)
#pragma unroll
        for (int q = 0; q < 4; ++q) acc[j][q] = 0.f;

    const uint32_t tb0 = (uint32_t)((((l >> 4) * 8) + (l & 7)) * 128 + ((l >> 3) & 1) * 16);
    const uint32_t swx = (uint32_t)((l & 7) << 4);

    for (int c = 0; c < NCHUNK; ++c) {
        if (c + 1 < NCHUNK) loadB(c + 1, (c + 1) & 1);
        cp_commit();
        cp_wait1();
        __syncthreads();

        const uint32_t bhiB = sb + (c & 1) * BUFB;
        const uint32_t bloB = bhiB + 16384;

#pragma unroll
        for (int kk = 0; kk < 4; ++kk) {
            uint32_t ahi[4], alo[4];
            splitf2(aN0, ahi[0], alo[0]);
            splitf2(aN1, ahi[1], alo[1]);
            splitf2(aN2, ahi[2], alo[2]);
            splitf2(aN3, ahi[3], alo[3]);

            int kn = c * 4 + kk + 1;
            if (kn < KTOT / 16) {
                int kb = kn * 16;
                aN0 = *(const float2*)(p0 + kb);
                aN1 = *(const float2*)(p1 + kb);
                aN2 = *(const float2*)(p0 + kb + 8);
                aN3 = *(const float2*)(p1 + kb + 8);
            }

#pragma unroll
            for (int jp = 0; jp < 8; ++jp) {
                uint32_t aoff = ((tb0 + (uint32_t)(kk * 32) + (uint32_t)(jp * 2048)) ^ swx);
                uint32_t bh[4], bl[4];
                ldsm4(bh, bhiB + aoff);
                ldsm4(bl, bloB + aoff);
                mma16816(acc[2 * jp],     ahi, bh[0], bh[1]);
                mma16816(acc[2 * jp],     ahi, bl[0], bl[1]);
                mma16816(acc[2 * jp],     alo, bh[0], bh[1]);
                mma16816(acc[2 * jp + 1], ahi, bh[2], bh[3]);
                mma16816(acc[2 * jp + 1], ahi, bl[2], bl[3]);
                mma16816(acc[2 * jp + 1], alo, bh[2], bh[3]);
            }
        }
        __syncthreads();
    }

    const int r0 = rowBase + w * 16 + (l >> 2);
    const int nb = colBase + (l & 3) * 2;
#pragma unroll
    for (int j = 0; j < 16; ++j) {
        int n = nb + j * 8;
        *(float2*)&out[(size_t)r0 * NN + n] = make_float2(acc[j][0], acc[j][1]);
        *(float2*)&out[(size_t)(r0 + 8) * NN + n] = make_float2(acc[j][2], acc[j][3]);
    }
}

// ---------------------------------------------------------------------------
extern "C" void kernel_launch(void* const* d_in, const int* in_sizes, int n_in,
                              void* d_out, int out_size)
{
    const float* x  = (const float*)d_in[0];
    const float* W1 = (const float*)d_in[1];
    const float* U1 = (const float*)d_in[2];
    const float* W2 = (const float*)d_in[3];
    const float* U2 = (const float*)d_in[4];
    const float* Wo = (const float*)d_in[5];
    float* out = (float*)d_out;

    cudaFuncSetAttribute(k_gemm_mma, cudaFuncAttributeMaxDynamicSharedMemorySize,
                         GEMM_SMEM);
    cudaFuncSetAttribute(k_afinal_tc, cudaFuncAttributeMaxDynamicSharedMemorySize,
                         128 * 132 * 4);

    k_init<<<MSZ / 256, 256>>>(U1, U2, W2);
    k_stage_tc<<<dim3(4, 3),  256>>>(1);
    k_stage_tc<<<dim3(4, 6),  256>>>(2);
    k_stage_tc<<<dim3(4, 12), 256>>>(4);
    k_stage_tc<<<dim3(4, 8),  256>>>(8);
    k_tmp_tc<<<dim3(4, 16), 256>>>(W1);
    k_afinal_tc<<<dim3(4, 16), 256, 128 * 132 * 4>>>(Wo);
    k_gemm_mma<<<dim3(BB / BM, NN / BN), 256, GEMM_SMEM>>>(x, out);
}

// round 6
// speedup vs baseline: 1.2800x; 1.2800x over previous
#include <cuda_runtime.h>
#include <cuda_bf16.h>
#include <cstdint>

// rnn_two: out = h2_last @ Wo for two stacked LINEAR SimpleRNNs.
// Linearity => out = sum_t x_t @ A_t with A_t = W1 @ S(15-t) @ Wo,
// S(m) = sum_{j=0..m} U1^j W2 U2^(m-j), via log-depth doubling.
// All matmuls on mma.sync bf16 hi/lo split (3 products, fp32 accum).
// Precompute B operands staged through SW128 smem + ldmatrix.trans;
// A fragments direct from gmem (coalesced).

#define NN 256
#define TT 16
#define MSZ (NN * NN)
#define BB 8192
#define KTOT (TT * NN)   // 4096

__device__ __align__(16) float g_P1[9][MSZ];
__device__ __align__(16) float g_P2[9][MSZ];
__device__ __align__(16) float g_S[TT][MSZ];
__device__ __align__(16) float g_TMP[TT][MSZ];
// Acat transposed + bf16-split: g_Bhi/lo[n][kglobal], kglobal = t*256 + j
__device__ __align__(16) __nv_bfloat16 g_Bhi[NN * KTOT];
__device__ __align__(16) __nv_bfloat16 g_Blo[NN * KTOT];

// ---------------------------------------------------------------------------
// Common helpers
// ---------------------------------------------------------------------------
__device__ __forceinline__ uint32_t s2u(const void* p) {
    uint32_t a;
    asm("{ .reg .u64 t; cvta.to.shared.u64 t, %1; cvt.u32.u64 %0, t; }"
        : "=r"(a) : "l"(p));
    return a;
}
__device__ __forceinline__ uint32_t sw128(uint32_t b) {
    return b ^ ((b >> 3) & 0x70);
}
__device__ __forceinline__ void cp16(uint32_t dst, const void* src) {
    asm volatile("cp.async.cg.shared.global [%0], [%1], 16;"
                 :: "r"(dst), "l"(src));
}
__device__ __forceinline__ void cp_commit() {
    asm volatile("cp.async.commit_group;");
}
__device__ __forceinline__ void cp_wait1() {
    asm volatile("cp.async.wait_group 1;" ::: "memory");
}
__device__ __forceinline__ void ldsm4(uint32_t r[4], uint32_t addr) {
    asm volatile("ldmatrix.sync.aligned.m8n8.x4.shared.b16 {%0,%1,%2,%3}, [%4];"
                 : "=r"(r[0]), "=r"(r[1]), "=r"(r[2]), "=r"(r[3]) : "r"(addr));
}
__device__ __forceinline__ void ldsm4t(uint32_t r[4], uint32_t addr) {
    asm volatile("ldmatrix.sync.aligned.m8n8.x4.trans.shared.b16 {%0,%1,%2,%3}, [%4];"
                 : "=r"(r[0]), "=r"(r[1]), "=r"(r[2]), "=r"(r[3]) : "r"(addr));
}
__device__ __forceinline__ void mma16816(float c[4], const uint32_t a[4],
                                         uint32_t b0, uint32_t b1) {
    asm volatile(
        "mma.sync.aligned.m16n8k16.row.col.f32.bf16.bf16.f32 "
        "{%0,%1,%2,%3}, {%4,%5,%6,%7}, {%8,%9}, {%0,%1,%2,%3};"
        : "+f"(c[0]), "+f"(c[1]), "+f"(c[2]), "+f"(c[3])
        : "r"(a[0]), "r"(a[1]), "r"(a[2]), "r"(a[3]), "r"(b0), "r"(b1));
}
__device__ __forceinline__ void splitf2(float2 v, uint32_t& hi, uint32_t& lo) {
    __nv_bfloat162 h = __float22bfloat162_rn(v);
    float2 hf = __bfloat1622float2(h);
    __nv_bfloat162 L = __float22bfloat162_rn(make_float2(v.x - hf.x, v.y - hf.y));
    hi = *reinterpret_cast<uint32_t*>(&h);
    lo = *reinterpret_cast<uint32_t*>(&L);
}

// ---------------------------------------------------------------------------
// Precompute matmul core: C_tile += A @ B  (256x256x256, fp32 gmem operands).
// CTA 128x128 (8 warps: 4m x 2n, each 32m x 64n). B staged per 64-k chunk:
// coalesced ldg -> regs -> bf16 split -> SW128 smem [k][n] -> ldmatrix.trans.
// smem layout per buffer (32KB): [hi s0 8K][hi s1 8K][lo s0 8K][lo s1 8K].
// ---------------------------------------------------------------------------
#define KC 64
#define PRE_BUF 32768
#define PRE_SMEM (2 * PRE_BUF)   // 64 KB

__device__ __forceinline__ void preB_ld(const float* __restrict__ B, int colBase,
                                        int c, int tid, float4 v[8]) {
#pragma unroll
    for (int p = 0; p < 8; ++p) {
        int id = tid + p * 256;
        int k = id >> 5, n = (id & 31) * 4;
        v[p] = *(const float4*)&B[(size_t)(c * KC + k) * NN + colBase + n];
    }
}
__device__ __forceinline__ void preB_st(char* buf, int tid, const float4 v[8]) {
#pragma unroll
    for (int p = 0; p < 8; ++p) {
        int id = tid + p * 256;
        int k = id >> 5, n = (id & 31) * 4;
        int s = n >> 6, nn = n & 63;
        uint32_t h0, l0, h1, l1;
        splitf2(make_float2(v[p].x, v[p].y), h0, l0);
        splitf2(make_float2(v[p].z, v[p].w), h1, l1);
        uint32_t off = (uint32_t)(s * 8192) + sw128((uint32_t)(k * 128 + nn * 2));
        *(uint2*)(buf + off) = make_uint2(h0, h1);
        *(uint2*)(buf + 16384 + off) = make_uint2(l0, l1);
    }
}

__device__ __forceinline__ void tc_mm_pre(
    float* acc,  // [2*8*4]
    const float* __restrict__ A, const float* __restrict__ B,
    char* smem, uint32_t sbu, int rowM, int colBase, int w, int lane, int tid)
{
    const int g = lane >> 2, t = lane & 3;
    const uint32_t subBase = (uint32_t)((w & 1) * 8192);
    const int krow = ((lane >> 3) & 1) * 8 + (lane & 7);
    const int nadd = ((lane >> 4) & 1) * 8;

    float4 breg[8];
    preB_ld(B, colBase, 0, tid, breg);

    for (int c = 0; c < NN / KC; ++c) {
        char* buf = smem + (c & 1) * PRE_BUF;
        preB_st(buf, tid, breg);
        __syncthreads();
        if (c + 1 < NN / KC) preB_ld(B, colBase, c + 1, tid, breg);

        const uint32_t bb = sbu + (uint32_t)((c & 1) * PRE_BUF) + subBase;
#pragma unroll
        for (int kk = 0; kk < 4; ++kk) {
            const int k0 = c * KC + kk * 16;
            uint32_t ahi[2][4], alo[2][4];
#pragma unroll
            for (int mt = 0; mt < 2; ++mt) {
                const float* p = A + (size_t)(rowM + mt * 16 + g) * NN + k0 + 2 * t;
                splitf2(*(const float2*)p,            ahi[mt][0], alo[mt][0]);
                splitf2(*(const float2*)(p + 8 * NN), ahi[mt][1], alo[mt][1]);
                splitf2(*(const float2*)(p + 8),      ahi[mt][2], alo[mt][2]);
                splitf2(*(const float2*)(p + 8 * NN + 8), ahi[mt][3], alo[mt][3]);
            }
#pragma unroll
            for (int jp2 = 0; jp2 < 4; ++jp2) {
                uint32_t off = sw128((uint32_t)((kk * 16 + krow) * 128 +
                                                (jp2 * 16 + nadd) * 2));
                uint32_t bh[4], bl[4];
                ldsm4t(bh, bb + off);
                ldsm4t(bl, bb + 16384 + off);
#pragma unroll
                for (int mt = 0; mt < 2; ++mt) {
                    float* c0 = acc + (mt * 8 + jp2 * 2) * 4;
                    float* c1 = acc + (mt * 8 + jp2 * 2 + 1) * 4;
                    mma16816(c0, ahi[mt], bh[0], bh[1]);
                    mma16816(c0, ahi[mt], bl[0], bl[1]);
                    mma16816(c0, alo[mt], bh[0], bh[1]);
                    mma16816(c1, ahi[mt], bh[2], bh[3]);
                    mma16816(c1, ahi[mt], bl[2], bl[3]);
                    mma16816(c1, alo[mt], bh[2], bh[3]);
                }
            }
        }
    }
    __syncthreads();
}

__device__ __forceinline__ void tc_store(
    const float* acc, float* __restrict__ C, int rowM, int colN, int lane)
{
    const int g = lane >> 2, t = lane & 3;
#pragma unroll
    for (int mt = 0; mt < 2; ++mt)
#pragma unroll
        for (int jp = 0; jp < 8; ++jp) {
            const float* c = acc + (mt * 8 + jp) * 4;
            int r = rowM + mt * 16 + g, col = colN + jp * 8 + 2 * t;
            *(float2*)&C[(size_t)r * NN + col] = make_float2(c[0], c[1]);
            *(float2*)&C[(size_t)(r + 8) * NN + col] = make_float2(c[2], c[3]);
        }
}

// ---------------------------------------------------------------------------
// Precompute kernels
// ---------------------------------------------------------------------------
__global__ void k_init(const float* __restrict__ U1,
                       const float* __restrict__ U2,
                       const float* __restrict__ W2)
{
    int i = blockIdx.x * blockDim.x + threadIdx.x;
    g_P1[1][i] = U1[i];
    g_P2[1][i] = U2[i];
    g_S[0][i]  = W2[i];
}

__global__ void __launch_bounds__(256) k_stage_tc(int M)
{
    extern __shared__ char smem[];
    const uint32_t sbu = s2u(smem);
    const int e_pow = min(M, 8 - M);
    const int job = blockIdx.y;
    const int tile = blockIdx.x;
    const int rowBase = (tile >> 1) * 128, colBase = (tile & 1) * 128;
    const int tid = threadIdx.x;
    const int w = tid >> 5, lane = tid & 31;
    const int rowM = rowBase + (w >> 1) * 32;
    const int colN = colBase + (w & 1) * 64;

    const float *A0, *B0, *A1 = nullptr, *B1 = nullptr;
    float* C;
    if (job < e_pow) {
        int j = job + 1;
        A0 = g_P1[M]; B0 = g_P1[j]; C = g_P1[M + j];
    } else if (job < 2 * e_pow) {
        int j = job - e_pow + 1;
        A0 = g_P2[M]; B0 = g_P2[j]; C = g_P2[M + j];
    } else {
        int m = M + (job - 2 * e_pow);
        A0 = g_S[M - 1]; B0 = g_P2[m - M + 1];
        A1 = g_P1[M];    B1 = g_S[m - M];
        C = g_S[m];
    }

    float acc[2 * 8 * 4] = {};
    tc_mm_pre(acc, A0, B0, smem, sbu, rowM, colBase, w, lane, tid);
    if (A1) tc_mm_pre(acc, A1, B1, smem, sbu, rowM, colBase, w, lane, tid);
    tc_store(acc, C, rowM, colN, lane);
}

__global__ void __launch_bounds__(256) k_tmp_tc(const float* __restrict__ W1)
{
    extern __shared__ char smem[];
    const uint32_t sbu = s2u(smem);
    const int m = blockIdx.y;
    const int tile = blockIdx.x;
    const int rowBase = (tile >> 1) * 128, colBase = (tile & 1) * 128;
    const int tid = threadIdx.x;
    const int w = tid >> 5, lane = tid & 31;
    const int rowM = rowBase + (w >> 1) * 32;
    const int colN = colBase + (w & 1) * 64;

    float acc[2 * 8 * 4] = {};
    tc_mm_pre(acc, W1, g_S[m], smem, sbu, rowM, colBase, w, lane, tid);
    tc_store(acc, g_TMP[m], rowM, colN, lane);
}

// A_t = TMP[15-t] @ Wo; emit transposed + bf16-split (smem reused for transpose).
__global__ void __launch_bounds__(256) k_afinal_tc(const float* __restrict__ Wo)
{
    extern __shared__ char smem[];
    const uint32_t sbu = s2u(smem);
    const int tIdx = blockIdx.y;
    const int tile = blockIdx.x;
    const int rowBase = (tile >> 1) * 128, colBase = (tile & 1) * 128;
    const int tid = threadIdx.x;
    const int w = tid >> 5, lane = tid & 31;
    const int rowM = rowBase + (w >> 1) * 32;
    const int colN = colBase + (w & 1) * 64;
    const int g = lane >> 2, t = lane & 3;

    float acc[2 * 8 * 4] = {};
    tc_mm_pre(acc, g_TMP[15 - tIdx], Wo, smem, sbu, rowM, colBase, w, lane, tid);

    // reuse smem as fp32 transpose buffer [128][132]
    float* cs = (float*)smem;
#pragma unroll
    for (int mt = 0; mt < 2; ++mt)
#pragma unroll
        for (int jp = 0; jp < 8; ++jp) {
            const float* c = acc + (mt * 8 + jp) * 4;
            int lr = (rowM - rowBase) + mt * 16 + g;
            int lc = (colN - colBase) + jp * 8 + 2 * t;
            cs[lr * 132 + lc] = c[0];
            cs[lr * 132 + lc + 1] = c[1];
            cs[(lr + 8) * 132 + lc] = c[2];
            cs[(lr + 8) * 132 + lc + 1] = c[3];
        }
    __syncthreads();

    for (int j = tid; j < 128 * 32; j += 256) {
        int n = j >> 5, m4 = j & 31;
        int kg = tIdx * NN + rowBase + m4 * 4;
        __nv_bfloat16 h[4], l[4];
#pragma unroll
        for (int r = 0; r < 4; ++r) {
            float v = cs[(m4 * 4 + r) * 132 + n];
            h[r] = __float2bfloat16_rn(v);
            l[r] = __float2bfloat16_rn(v - __bfloat162float(h[r]));
        }
        *(uint64_t*)&g_Bhi[(size_t)(colBase + n) * KTOT + kg] = *(uint64_t*)h;
        *(uint64_t*)&g_Blo[(size_t)(colBase + n) * KTOT + kg] = *(uint64_t*)l;
    }
}

// ---------------------------------------------------------------------------
// Main GEMM on mma.sync: out[8192,256] = X @ Acat. (validated in R3)
// ---------------------------------------------------------------------------
#define BM 128
#define BN 128
#define BKC 64
#define NCHUNK (KTOT / BKC)
#define BUFB 32768
#define GEMM_SMEM (2 * BUFB)

__global__ void __launch_bounds__(256)
k_gemm_mma(const float* __restrict__ X, float* __restrict__ out)
{
    extern __shared__ char smem[];
    const uint32_t sb = s2u(smem);
    const int tid = threadIdx.x;
    const int w = tid >> 5, l = tid & 31;
    const int rowBase = blockIdx.x * BM;
    const int colBase = blockIdx.y * BN;

    auto loadB = [&](int c, int b) {
        const uint32_t dhi = sb + b * BUFB;
        const uint32_t dlo = dhi + 16384;
#pragma unroll
        for (int p = 0; p < 4; ++p) {
            int id = tid + p * 256;
            int n = id >> 3, cc = id & 7;
            uint32_t off = sw128((uint32_t)(n * 128 + cc * 16));
            size_t gidx = (size_t)(colBase + n) * KTOT + c * BKC + cc * 8;
            cp16(dhi + off, &g_Bhi[gidx]);
            cp16(dlo + off, &g_Blo[gidx]);
        }
    };

    loadB(0, 0);
    cp_commit();

    const float* p0 = X + (size_t)(rowBase + w * 16 + (l >> 2)) * KTOT + (l & 3) * 2;
    const float* p1 = p0 + (size_t)8 * KTOT;

    float2 aN0 = *(const float2*)(p0);
    float2 aN1 = *(const float2*)(p1);
    float2 aN2 = *(const float2*)(p0 + 8);
    float2 aN3 = *(const float2*)(p1 + 8);

    float acc[16][4];
#pragma unroll
    for (int j = 0; j < 16; ++j)
#pragma unroll
        for (int q = 0; q < 4; ++q) acc[j][q] = 0.f;

    const uint32_t tb0 = (uint32_t)((((l >> 4) * 8) + (l & 7)) * 128 + ((l >> 3) & 1) * 16);
    const uint32_t swx = (uint32_t)((l & 7) << 4);

    for (int c = 0; c < NCHUNK; ++c) {
        if (c + 1 < NCHUNK) loadB(c + 1, (c + 1) & 1);
        cp_commit();
        cp_wait1();
        __syncthreads();

        const uint32_t bhiB = sb + (c & 1) * BUFB;
        const uint32_t bloB = bhiB + 16384;

#pragma unroll
        for (int kk = 0; kk < 4; ++kk) {
            uint32_t ahi[4], alo[4];
            splitf2(aN0, ahi[0], alo[0]);
            splitf2(aN1, ahi[1], alo[1]);
            splitf2(aN2, ahi[2], alo[2]);
            splitf2(aN3, ahi[3], alo[3]);

            int kn = c * 4 + kk + 1;
            if (kn < KTOT / 16) {
                int kb = kn * 16;
                aN0 = *(const float2*)(p0 + kb);
                aN1 = *(const float2*)(p1 + kb);
                aN2 = *(const float2*)(p0 + kb + 8);
                aN3 = *(const float2*)(p1 + kb + 8);
            }

#pragma unroll
            for (int jp = 0; jp < 8; ++jp) {
                uint32_t aoff = ((tb0 + (uint32_t)(kk * 32) + (uint32_t)(jp * 2048)) ^ swx);
                uint32_t bh[4], bl[4];
                ldsm4(bh, bhiB + aoff);
                ldsm4(bl, bloB + aoff);
                mma16816(acc[2 * jp],     ahi, bh[0], bh[1]);
                mma16816(acc[2 * jp],     ahi, bl[0], bl[1]);
                mma16816(acc[2 * jp],     alo, bh[0], bh[1]);
                mma16816(acc[2 * jp + 1], ahi, bh[2], bh[3]);
                mma16816(acc[2 * jp + 1], ahi, bl[2], bl[3]);
                mma16816(acc[2 * jp + 1], alo, bh[2], bh[3]);
            }
        }
        __syncthreads();
    }

    const int r0 = rowBase + w * 16 + (l >> 2);
    const int nb = colBase + (l & 3) * 2;
#pragma unroll
    for (int j = 0; j < 16; ++j) {
        int n = nb + j * 8;
        *(float2*)&out[(size_t)r0 * NN + n] = make_float2(acc[j][0], acc[j][1]);
        *(float2*)&out[(size_t)(r0 + 8) * NN + n] = make_float2(acc[j][2], acc[j][3]);
    }
}

// ---------------------------------------------------------------------------
extern "C" void kernel_launch(void* const* d_in, const int* in_sizes, int n_in,
                              void* d_out, int out_size)
{
    const float* x  = (const float*)d_in[0];
    const float* W1 = (const float*)d_in[1];
    const float* U1 = (const float*)d_in[2];
    const float* W2 = (const float*)d_in[3];
    const float* U2 = (const float*)d_in[4];
    const float* Wo = (const float*)d_in[5];
    float* out = (float*)d_out;

    const int AF_SMEM = 128 * 132 * 4;   // 67584 >= PRE_SMEM
    cudaFuncSetAttribute(k_gemm_mma, cudaFuncAttributeMaxDynamicSharedMemorySize,
                         GEMM_SMEM);
    cudaFuncSetAttribute(k_stage_tc, cudaFuncAttributeMaxDynamicSharedMemorySize,
                         PRE_SMEM);
    cudaFuncSetAttribute(k_tmp_tc, cudaFuncAttributeMaxDynamicSharedMemorySize,
                         PRE_SMEM);
    cudaFuncSetAttribute(k_afinal_tc, cudaFuncAttributeMaxDynamicSharedMemorySize,
                         AF_SMEM);

    k_init<<<MSZ / 256, 256>>>(U1, U2, W2);
    k_stage_tc<<<dim3(4, 3),  256, PRE_SMEM>>>(1);
    k_stage_tc<<<dim3(4, 6),  256, PRE_SMEM>>>(2);
    k_stage_tc<<<dim3(4, 12), 256, PRE_SMEM>>>(4);
    k_stage_tc<<<dim3(4, 8),  256, PRE_SMEM>>>(8);
    k_tmp_tc<<<dim3(4, 16), 256, PRE_SMEM>>>(W1);
    k_afinal_tc<<<dim3(4, 16), 256, AF_SMEM>>>(Wo);
    k_gemm_mma<<<dim3(BB / BM, NN / BN), 256, GEMM_SMEM>>>(x, out);
}

// round 8
// speedup vs baseline: 1.4177x; 1.1076x over previous
#include <cuda_runtime.h>
#include <cuda_bf16.h>
#include <cstdint>

// rnn_two: out = h2_last @ Wo for two stacked LINEAR SimpleRNNs.
// Linearity => out = sum_t x_t @ A_t with A_t = W1 @ S(15-t) @ Wo,
// S(m) = sum_{j=0..m} U1^j W2 U2^(m-j), via log-depth doubling.
// All matmuls on mma.sync bf16 hi/lo split (3 products, fp32 accum).
// Precompute retiled to 64x64 CTAs (16 CTAs per matmul) for SM coverage.

#define NN 256
#define TT 16
#define MSZ (NN * NN)
#define BB 8192
#define KTOT (TT * NN)   // 4096

__device__ __align__(16) float g_P1[9][MSZ];
__device__ __align__(16) float g_P2[9][MSZ];
__device__ __align__(16) float g_S[TT][MSZ];
__device__ __align__(16) float g_TMP[TT][MSZ];
// Acat transposed + bf16-split: g_Bhi/lo[n][kglobal], kglobal = t*256 + j
__device__ __align__(16) __nv_bfloat16 g_Bhi[NN * KTOT];
__device__ __align__(16) __nv_bfloat16 g_Blo[NN * KTOT];

// ---------------------------------------------------------------------------
// Common helpers
// ---------------------------------------------------------------------------
__device__ __forceinline__ uint32_t s2u(const void* p) {
    uint32_t a;
    asm("{ .reg .u64 t; cvta.to.shared.u64 t, %1; cvt.u32.u64 %0, t; }"
        : "=r"(a) : "l"(p));
    return a;
}
__device__ __forceinline__ uint32_t sw128(uint32_t b) {
    return b ^ ((b >> 3) & 0x70);
}
__device__ __forceinline__ void cp16(uint32_t dst, const void* src) {
    asm volatile("cp.async.cg.shared.global [%0], [%1], 16;"
                 :: "r"(dst), "l"(src));
}
__device__ __forceinline__ void cp_commit() {
    asm volatile("cp.async.commit_group;");
}
__device__ __forceinline__ void cp_wait1() {
    asm volatile("cp.async.wait_group 1;" ::: "memory");
}
__device__ __forceinline__ void ldsm4(uint32_t r[4], uint32_t addr) {
    asm volatile("ldmatrix.sync.aligned.m8n8.x4.shared.b16 {%0,%1,%2,%3}, [%4];"
                 : "=r"(r[0]), "=r"(r[1]), "=r"(r[2]), "=r"(r[3]) : "r"(addr));
}
__device__ __forceinline__ void ldsm4t(uint32_t r[4], uint32_t addr) {
    asm volatile("ldmatrix.sync.aligned.m8n8.x4.trans.shared.b16 {%0,%1,%2,%3}, [%4];"
                 : "=r"(r[0]), "=r"(r[1]), "=r"(r[2]), "=r"(r[3]) : "r"(addr));
}
__device__ __forceinline__ void mma16816(float c[4], const uint32_t a[4],
                                         uint32_t b0, uint32_t b1) {
    asm volatile(
        "mma.sync.aligned.m16n8k16.row.col.f32.bf16.bf16.f32 "
        "{%0,%1,%2,%3}, {%4,%5,%6,%7}, {%8,%9}, {%0,%1,%2,%3};"
        : "+f"(c[0]), "+f"(c[1]), "+f"(c[2]), "+f"(c[3])
        : "r"(a[0]), "r"(a[1]), "r"(a[2]), "r"(a[3]), "r"(b0), "r"(b1));
}
__device__ __forceinline__ void splitf2(float2 v, uint32_t& hi, uint32_t& lo) {
    __nv_bfloat162 h = __float22bfloat162_rn(v);
    float2 hf = __bfloat1622float2(h);
    __nv_bfloat162 L = __float22bfloat162_rn(make_float2(v.x - hf.x, v.y - hf.y));
    hi = *reinterpret_cast<uint32_t*>(&h);
    lo = *reinterpret_cast<uint32_t*>(&L);
}

// ---------------------------------------------------------------------------
// Precompute matmul core: 64x64 CTA tile, 128 threads (4 warps, warp=32x32).
// B staged per 64-k chunk: coalesced ldg -> regs -> bf16 split -> SW128
// smem [k][n] (row = 64 bf16 = 128B) -> ldmatrix.trans.
// smem: double buffer, each 16KB = [hi 8KB][lo 8KB].
// ---------------------------------------------------------------------------
#define KC 64
#define PB_SLAB 8192
#define PRE_BUF 16384
#define PRE_SMEM 32768

__device__ __forceinline__ void preB_ld(const float* __restrict__ B, int colBase,
                                        int c, int tid, float4 v[8]) {
#pragma unroll
    for (int p = 0; p < 8; ++p) {
        int id = tid + p * 128;          // 1024 float4 = 64k x 64n
        int k = id >> 4, n4 = id & 15;
        v[p] = *(const float4*)&B[(size_t)(c * KC + k) * NN + colBase + n4 * 4];
    }
}
__device__ __forceinline__ void preB_st(char* buf, int tid, const float4 v[8]) {
#pragma unroll
    for (int p = 0; p < 8; ++p) {
        int id = tid + p * 128;
        int k = id >> 4, n4 = id & 15;
        uint32_t h0, l0, h1, l1;
        splitf2(make_float2(v[p].x, v[p].y), h0, l0);
        splitf2(make_float2(v[p].z, v[p].w), h1, l1);
        uint32_t off = sw128((uint32_t)(k * 128 + n4 * 8));
        *(uint2*)(buf + off) = make_uint2(h0, h1);
        *(uint2*)(buf + PB_SLAB + off) = make_uint2(l0, l1);
    }
}

__device__ __forceinline__ void tc_mm_pre(
    float* acc,  // [2mt][4jp][4] = 32
    const float* __restrict__ A, const float* __restrict__ B,
    char* smem, uint32_t sbu, int rowM, int colBase, int colW, int lane, int tid)
{
    const int g = lane >> 2, t = lane & 3;
    const int krow = ((lane >> 3) & 1) * 8 + (lane & 7);
    const int nadd = ((lane >> 4) & 1) * 8;

    float4 breg[8];
    preB_ld(B, colBase, 0, tid, breg);

    for (int c = 0; c < NN / KC; ++c) {
        char* buf = smem + (c & 1) * PRE_BUF;
        preB_st(buf, tid, breg);
        __syncthreads();
        if (c + 1 < NN / KC) preB_ld(B, colBase, c + 1, tid, breg);

        const uint32_t bb = sbu + (uint32_t)((c & 1) * PRE_BUF);
#pragma unroll
        for (int kk = 0; kk < 4; ++kk) {
            const int k0 = c * KC + kk * 16;
            uint32_t ahi[2][4], alo[2][4];
#pragma unroll
            for (int mt = 0; mt < 2; ++mt) {
                const float* p = A + (size_t)(rowM + mt * 16 + g) * NN + k0 + 2 * t;
                splitf2(*(const float2*)p,                ahi[mt][0], alo[mt][0]);
                splitf2(*(const float2*)(p + 8 * NN),     ahi[mt][1], alo[mt][1]);
                splitf2(*(const float2*)(p + 8),          ahi[mt][2], alo[mt][2]);
                splitf2(*(const float2*)(p + 8 * NN + 8), ahi[mt][3], alo[mt][3]);
            }
#pragma unroll
            for (int jp2 = 0; jp2 < 2; ++jp2) {
                uint32_t off = sw128((uint32_t)((kk * 16 + krow) * 128 +
                                                (colW + jp2 * 16 + nadd) * 2));
                uint32_t bh[4], bl[4];
                ldsm4t(bh, bb + off);
                ldsm4t(bl, bb + PB_SLAB + off);
#pragma unroll
                for (int mt = 0; mt < 2; ++mt) {
                    float* c0 = acc + (mt * 4 + jp2 * 2) * 4;
                    float* c1 = acc + (mt * 4 + jp2 * 2 + 1) * 4;
                    mma16816(c0, ahi[mt], bh[0], bh[1]);
                    mma16816(c0, ahi[mt], bl[0], bl[1]);
                    mma16816(c0, alo[mt], bh[0], bh[1]);
                    mma16816(c1, ahi[mt], bh[2], bh[3]);
                    mma16816(c1, ahi[mt], bl[2], bl[3]);
                    mma16816(c1, alo[mt], bh[2], bh[3]);
                }
            }
        }
        __syncthreads();
    }
}

__device__ __forceinline__ void tc_store(
    const float* acc, float* __restrict__ C, int rowM, int colN, int lane)
{
    const int g = lane >> 2, t = lane & 3;
#pragma unroll
    for (int mt = 0; mt < 2; ++mt)
#pragma unroll
        for (int jp = 0; jp < 4; ++jp) {
            const float* c = acc + (mt * 4 + jp) * 4;
            int r = rowM + mt * 16 + g, col = colN + jp * 8 + 2 * t;
            *(float2*)&C[(size_t)r * NN + col] = make_float2(c[0], c[1]);
            *(float2*)&C[(size_t)(r + 8) * NN + col] = make_float2(c[2], c[3]);
        }
}

// ---------------------------------------------------------------------------
// Precompute kernels. Tile: blockIdx.x in [0,16): row=(x>>2)*64, col=(x&3)*64.
// Warp layout in 128-thread CTA: rowM += (w&1)*32, colW = (w>>1)*32.
// ---------------------------------------------------------------------------
__global__ void k_init(const float* __restrict__ U1,
                       const float* __restrict__ U2,
                       const float* __restrict__ W2)
{
    int i = blockIdx.x * blockDim.x + threadIdx.x;
    g_P1[1][i] = U1[i];
    g_P2[1][i] = U2[i];
    g_S[0][i]  = W2[i];
}

__global__ void __launch_bounds__(128) k_stage_tc(int M)
{
    extern __shared__ char smem[];
    const uint32_t sbu = s2u(smem);
    const int e_pow = min(M, 8 - M);
    const int job = blockIdx.y;
    const int tile = blockIdx.x;
    const int rowBase = (tile >> 2) * 64, colBase = (tile & 3) * 64;
    const int tid = threadIdx.x;
    const int w = tid >> 5, lane = tid & 31;
    const int rowM = rowBase + (w & 1) * 32;
    const int colW = (w >> 1) * 32;

    const float *A0, *B0, *A1 = nullptr, *B1 = nullptr;
    float* C;
    if (job < e_pow) {
        int j = job + 1;
        A0 = g_P1[M]; B0 = g_P1[j]; C = g_P1[M + j];
    } else if (job < 2 * e_pow) {
        int j = job - e_pow + 1;
        A0 = g_P2[M]; B0 = g_P2[j]; C = g_P2[M + j];
    } else {
        int m = M + (job - 2 * e_pow);
        A0 = g_S[M - 1]; B0 = g_P2[m - M + 1];
        A1 = g_P1[M];    B1 = g_S[m - M];
        C = g_S[m];
    }

    float acc[32] = {};
    tc_mm_pre(acc, A0, B0, smem, sbu, rowM, colBase, colW, lane, tid);
    if (A1) tc_mm_pre(acc, A1, B1, smem, sbu, rowM, colBase, colW, lane, tid);
    tc_store(acc, C, rowM, colBase + colW, lane);
}

__global__ void __launch_bounds__(128) k_tmp_tc(const float* __restrict__ W1)
{
    extern __shared__ char smem[];
    const uint32_t sbu = s2u(smem);
    const int m = blockIdx.y;
    const int tile = blockIdx.x;
    const int rowBase = (tile >> 2) * 64, colBase = (tile & 3) * 64;
    const int tid = threadIdx.x;
    const int w = tid >> 5, lane = tid & 31;
    const int rowM = rowBase + (w & 1) * 32;
    const int colW = (w >> 1) * 32;

    float acc[32] = {};
    tc_mm_pre(acc, W1, g_S[m], smem, sbu, rowM, colBase, colW, lane, tid);
    tc_store(acc, g_TMP[m], rowM, colBase + colW, lane);
}

// A_t = TMP[15-t] @ Wo; emit transposed + bf16-split (smem reused, [64][68]).
__global__ void __launch_bounds__(128) k_afinal_tc(const float* __restrict__ Wo)
{
    extern __shared__ char smem[];
    const uint32_t sbu = s2u(smem);
    const int tIdx = blockIdx.y;
    const int tile = blockIdx.x;
    const int rowBase = (tile >> 2) * 64, colBase = (tile & 3) * 64;
    const int tid = threadIdx.x;
    const int w = tid >> 5, lane = tid & 31;
    const int rowM = rowBase + (w & 1) * 32;
    const int colW = (w >> 1) * 32;
    const int g = lane >> 2, t = lane & 3;

    float acc[32] = {};
    tc_mm_pre(acc, g_TMP[15 - tIdx], Wo, smem, sbu, rowM, colBase, colW, lane, tid);

    float* cs = (float*)smem;   // [64][68]
#pragma unroll
    for (int mt = 0; mt < 2; ++mt)
#pragma unroll
        for (int jp = 0; jp < 4; ++jp) {
            const float* c = acc + (mt * 4 + jp) * 4;
            int lr = (w & 1) * 32 + mt * 16 + g;
            int lc = colW + jp * 8 + 2 * t;
            cs[lr * 68 + lc] = c[0];
            cs[lr * 68 + lc + 1] = c[1];
            cs[(lr + 8) * 68 + lc] = c[2];
            cs[(lr + 8) * 68 + lc + 1] = c[3];
        }
    __syncthreads();

    for (int j = tid; j < 64 * 16; j += 128) {
        int n = j >> 4, m4 = j & 15;
        int kg = tIdx * NN + rowBase + m4 * 4;
        __nv_bfloat16 h[4], l[4];
#pragma unroll
        for (int r = 0; r < 4; ++r) {
            float v = cs[(m4 * 4 + r) * 68 + n];
            h[r] = __float2bfloat16_rn(v);
            l[r] = __float2bfloat16_rn(v - __bfloat162float(h[r]));
        }
        *(uint64_t*)&g_Bhi[(size_t)(colBase + n) * KTOT + kg] = *(uint64_t*)h;
        *(uint64_t*)&g_Blo[(size_t)(colBase + n) * KTOT + kg] = *(uint64_t*)l;
    }
}

// ---------------------------------------------------------------------------
// Main GEMM on mma.sync: out[8192,256] = X @ Acat. (validated in R3/R6)
// ---------------------------------------------------------------------------
#define BM 128
#define BN 128
#define BKC 64
#define NCHUNK (KTOT / BKC)
#define BUFB 32768
#define GEMM_SMEM (2 * BUFB)

__global__ void __launch_bounds__(256)
k_gemm_mma(const float* __restrict__ X, float* __restrict__ out)
{
    extern __shared__ char smem[];
    const uint32_t sb = s2u(smem);
    const int tid = threadIdx.x;
    const int w = tid >> 5, l = tid & 31;
    const int rowBase = blockIdx.x * BM;
    const int colBase = blockIdx.y * BN;

    auto loadB = [&](int c, int b) {
        const uint32_t dhi = sb + b * BUFB;
        const uint32_t dlo = dhi + 16384;
#pragma unroll
        for (int p = 0; p < 4; ++p) {
            int id = tid + p * 256;
            int n = id >> 3, cc = id & 7;
            uint32_t off = sw128((uint32_t)(n * 128 + cc * 16));
            size_t gidx = (size_t)(colBase + n) * KTOT + c * BKC + cc * 8;
            cp16(dhi + off, &g_Bhi[gidx]);
            cp16(dlo + off, &g_Blo[gidx]);
        }
    };

    loadB(0, 0);
    cp_commit();

    const float* p0 = X + (size_t)(rowBase + w * 16 + (l >> 2)) * KTOT + (l & 3) * 2;
    const float* p1 = p0 + (size_t)8 * KTOT;

    float2 aN0 = *(const float2*)(p0);
    float2 aN1 = *(const float2*)(p1);
    float2 aN2 = *(const float2*)(p0 + 8);
    float2 aN3 = *(const float2*)(p1 + 8);

    float acc[16][4];
#pragma unroll
    for (int j = 0; j < 16; ++j)
#pragma unroll
        for (int q = 0; q < 4; ++q) acc[j][q] = 0.f;

    const uint32_t tb0 = (uint32_t)((((l >> 4) * 8) + (l & 7)) * 128 + ((l >> 3) & 1) * 16);
    const uint32_t swx = (uint32_t)((l & 7) << 4);

    for (int c = 0; c < NCHUNK; ++c) {
        if (c + 1 < NCHUNK) loadB(c + 1, (c + 1) & 1);
        cp_commit();
        cp_wait1();
        __syncthreads();

        const uint32_t bhiB = sb + (c & 1) * BUFB;
        const uint32_t bloB = bhiB + 16384;

#pragma unroll
        for (int kk = 0; kk < 4; ++kk) {
            uint32_t ahi[4], alo[4];
            splitf2(aN0, ahi[0], alo[0]);
            splitf2(aN1, ahi[1], alo[1]);
            splitf2(aN2, ahi[2], alo[2]);
            splitf2(aN3, ahi[3], alo[3]);

            int kn = c * 4 + kk + 1;
            if (kn < KTOT / 16) {
                int kb = kn * 16;
                aN0 = *(const float2*)(p0 + kb);
                aN1 = *(const float2*)(p1 + kb);
                aN2 = *(const float2*)(p0 + kb + 8);
                aN3 = *(const float2*)(p1 + kb + 8);
            }

#pragma unroll
            for (int jp = 0; jp < 8; ++jp) {
                uint32_t aoff = ((tb0 + (uint32_t)(kk * 32) + (uint32_t)(jp * 2048)) ^ swx);
                uint32_t bh[4], bl[4];
                ldsm4(bh, bhiB + aoff);
                ldsm4(bl, bloB + aoff);
                mma16816(acc[2 * jp],     ahi, bh[0], bh[1]);
                mma16816(acc[2 * jp],     ahi, bl[0], bl[1]);
                mma16816(acc[2 * jp],     alo, bh[0], bh[1]);
                mma16816(acc[2 * jp + 1], ahi, bh[2], bh[3]);
                mma16816(acc[2 * jp + 1], ahi, bl[2], bl[3]);
                mma16816(acc[2 * jp + 1], alo, bh[2], bh[3]);
            }
        }
        __syncthreads();
    }

    const int r0 = rowBase + w * 16 + (l >> 2);
    const int nb = colBase + (l & 3) * 2;
#pragma unroll
    for (int j = 0; j < 16; ++j) {
        int n = nb + j * 8;
        *(float2*)&out[(size_t)r0 * NN + n] = make_float2(acc[j][0], acc[j][1]);
        *(float2*)&out[(size_t)(r0 + 8) * NN + n] = make_float2(acc[j][2], acc[j][3]);
    }
}

// ---------------------------------------------------------------------------
extern "C" void kernel_launch(void* const* d_in, const int* in_sizes, int n_in,
                              void* d_out, int out_size)
{
    const float* x  = (const float*)d_in[0];
    const float* W1 = (const float*)d_in[1];
    const float* U1 = (const float*)d_in[2];
    const float* W2 = (const float*)d_in[3];
    const float* U2 = (const float*)d_in[4];
    const float* Wo = (const float*)d_in[5];
    float* out = (float*)d_out;

    cudaFuncSetAttribute(k_gemm_mma, cudaFuncAttributeMaxDynamicSharedMemorySize,
                         GEMM_SMEM);
    cudaFuncSetAttribute(k_stage_tc, cudaFuncAttributeMaxDynamicSharedMemorySize,
                         PRE_SMEM);
    cudaFuncSetAttribute(k_tmp_tc, cudaFuncAttributeMaxDynamicSharedMemorySize,
                         PRE_SMEM);
    cudaFuncSetAttribute(k_afinal_tc, cudaFuncAttributeMaxDynamicSharedMemorySize,
                         PRE_SMEM);

    k_init<<<MSZ / 256, 256>>>(U1, U2, W2);
    k_stage_tc<<<dim3(16, 3),  128, PRE_SMEM>>>(1);
    k_stage_tc<<<dim3(16, 6),  128, PRE_SMEM>>>(2);
    k_stage_tc<<<dim3(16, 12), 128, PRE_SMEM>>>(4);
    k_stage_tc<<<dim3(16, 8),  128, PRE_SMEM>>>(8);
    k_tmp_tc<<<dim3(16, 16), 128, PRE_SMEM>>>(W1);
    k_afinal_tc<<<dim3(16, 16), 128, PRE_SMEM>>>(Wo);
    k_gemm_mma<<<dim3(BB / BM, NN / BN), 256, GEMM_SMEM>>>(x, out);
}

// round 9
// speedup vs baseline: 1.5236x; 1.0747x over previous
#include <cuda_runtime.h>
#include <cuda_bf16.h>
#include <cstdint>

// rnn_two: out = h2_last @ Wo for two stacked LINEAR SimpleRNNs.
// Linearity => out = sum_t x_t @ A_t with A_t = W1 @ S(15-t) @ Wo,
// S(m) = sum_{j=0..m} U1^j W2 U2^(m-j), via log-depth doubling.
// All matmuls on mma.sync bf16 hi/lo split (3 products, fp32 accum).
// Precompute fused into ONE persistent kernel (global software barrier
// between phases) with A-register prefetch to hide L2 latency.

#define NN 256
#define TT 16
#define MSZ (NN * NN)
#define BB 8192
#define KTOT (TT * NN)   // 4096
#define NCTA 256         // persistent grid; residency guaranteed (see launch_bounds)

__device__ __align__(16) float g_P1[9][MSZ];
__device__ __align__(16) float g_P2[9][MSZ];
__device__ __align__(16) float g_S[TT][MSZ];
__device__ __align__(16) float g_TMP[TT][MSZ];
// Acat transposed + bf16-split: g_Bhi/lo[n][kglobal], kglobal = t*256 + j
__device__ __align__(16) __nv_bfloat16 g_Bhi[NN * KTOT];
__device__ __align__(16) __nv_bfloat16 g_Blo[NN * KTOT];

// global barrier state (BSS zero; cnt returns to 0 after each barrier,
// sense is monotonic and read relative at kernel start -> replay-safe)
__device__ int g_cnt;
__device__ volatile int g_sense;

// ---------------------------------------------------------------------------
// Common helpers
// ---------------------------------------------------------------------------
__device__ __forceinline__ uint32_t s2u(const void* p) {
    uint32_t a;
    asm("{ .reg .u64 t; cvta.to.shared.u64 t, %1; cvt.u32.u64 %0, t; }"
        : "=r"(a) : "l"(p));
    return a;
}
__device__ __forceinline__ uint32_t sw128(uint32_t b) {
    return b ^ ((b >> 3) & 0x70);
}
__device__ __forceinline__ void cp16(uint32_t dst, const void* src) {
    asm volatile("cp.async.cg.shared.global [%0], [%1], 16;"
                 :: "r"(dst), "l"(src));
}
__device__ __forceinline__ void cp_commit() {
    asm volatile("cp.async.commit_group;");
}
__device__ __forceinline__ void cp_wait1() {
    asm volatile("cp.async.wait_group 1;" ::: "memory");
}
__device__ __forceinline__ void ldsm4(uint32_t r[4], uint32_t addr) {
    asm volatile("ldmatrix.sync.aligned.m8n8.x4.shared.b16 {%0,%1,%2,%3}, [%4];"
                 : "=r"(r[0]), "=r"(r[1]), "=r"(r[2]), "=r"(r[3]) : "r"(addr));
}
__device__ __forceinline__ void ldsm4t(uint32_t r[4], uint32_t addr) {
    asm volatile("ldmatrix.sync.aligned.m8n8.x4.trans.shared.b16 {%0,%1,%2,%3}, [%4];"
                 : "=r"(r[0]), "=r"(r[1]), "=r"(r[2]), "=r"(r[3]) : "r"(addr));
}
__device__ __forceinline__ void mma16816(float c[4], const uint32_t a[4],
                                         uint32_t b0, uint32_t b1) {
    asm volatile(
        "mma.sync.aligned.m16n8k16.row.col.f32.bf16.bf16.f32 "
        "{%0,%1,%2,%3}, {%4,%5,%6,%7}, {%8,%9}, {%0,%1,%2,%3};"
        : "+f"(c[0]), "+f"(c[1]), "+f"(c[2]), "+f"(c[3])
        : "r"(a[0]), "r"(a[1]), "r"(a[2]), "r"(a[3]), "r"(b0), "r"(b1));
}
__device__ __forceinline__ void splitf2(float2 v, uint32_t& hi, uint32_t& lo) {
    __nv_bfloat162 h = __float22bfloat162_rn(v);
    float2 hf = __bfloat1622float2(h);
    __nv_bfloat162 L = __float22bfloat162_rn(make_float2(v.x - hf.x, v.y - hf.y));
    hi = *reinterpret_cast<uint32_t*>(&h);
    lo = *reinterpret_cast<uint32_t*>(&L);
}

// ---------------------------------------------------------------------------
// Precompute matmul core: 64x64 CTA tile, 128 threads (4 warps, warp=32x32).
// B: coalesced ldg -> regs -> bf16 split -> SW128 smem [k][n] -> ldmatrix.trans
//    (double buffer, each 16KB = [hi 8KB][lo 8KB]).
// A: direct gmem float2 fragments with one-k16-ahead register prefetch.
// ---------------------------------------------------------------------------
#define KC 64
#define PB_SLAB 8192
#define PRE_BUF 16384
#define PRE_SMEM 32768

__device__ __forceinline__ void preB_ld(const float* __restrict__ B, int colBase,
                                        int c, int tid, float4 v[8]) {
#pragma unroll
    for (int p = 0; p < 8; ++p) {
        int id = tid + p * 128;          // 1024 float4 = 64k x 64n
        int k = id >> 4, n4 = id & 15;
        v[p] = *(const float4*)&B[(size_t)(c * KC + k) * NN + colBase + n4 * 4];
    }
}
__device__ __forceinline__ void preB_st(char* buf, int tid, const float4 v[8]) {
#pragma unroll
    for (int p = 0; p < 8; ++p) {
        int id = tid + p * 128;
        int k = id >> 4, n4 = id & 15;
        uint32_t h0, l0, h1, l1;
        splitf2(make_float2(v[p].x, v[p].y), h0, l0);
        splitf2(make_float2(v[p].z, v[p].w), h1, l1);
        uint32_t off = sw128((uint32_t)(k * 128 + n4 * 8));
        *(uint2*)(buf + off) = make_uint2(h0, h1);
        *(uint2*)(buf + PB_SLAB + off) = make_uint2(l0, l1);
    }
}
__device__ __forceinline__ void loadA8(float2 af[8], const float* __restrict__ A,
                                       int rowM, int k0, int g, int t) {
#pragma unroll
    for (int mt = 0; mt < 2; ++mt) {
        const float* p = A + (size_t)(rowM + mt * 16 + g) * NN + k0 + 2 * t;
        af[mt * 4 + 0] = *(const float2*)p;
        af[mt * 4 + 1] = *(const float2*)(p + 8 * NN);
        af[mt * 4 + 2] = *(const float2*)(p + 8);
        af[mt * 4 + 3] = *(const float2*)(p + 8 * NN + 8);
    }
}

__device__ __forceinline__ void tc_mm_pre(
    float* acc,  // [2mt][4jp][4] = 32
    const float* __restrict__ A, const float* __restrict__ B,
    char* smem, uint32_t sbu, int rowM, int colBase, int colW, int lane, int tid)
{
    const int g = lane >> 2, t = lane & 3;
    const int krow = ((lane >> 3) & 1) * 8 + (lane & 7);
    const int nadd = ((lane >> 4) & 1) * 8;

    float4 breg[8];
    preB_ld(B, colBase, 0, tid, breg);
    float2 af[8];
    loadA8(af, A, rowM, 0, g, t);

    for (int c = 0; c < NN / KC; ++c) {
        char* buf = smem + (c & 1) * PRE_BUF;
        preB_st(buf, tid, breg);
        __syncthreads();
        if (c + 1 < NN / KC) preB_ld(B, colBase, c + 1, tid, breg);

        const uint32_t bb = sbu + (uint32_t)((c & 1) * PRE_BUF);
#pragma unroll
        for (int kk = 0; kk < 4; ++kk) {
            uint32_t ahi[2][4], alo[2][4];
#pragma unroll
            for (int q = 0; q < 8; ++q)
                splitf2(af[q], ahi[q >> 2][q & 3], alo[q >> 2][q & 3]);

            int kgn = c * 4 + kk + 1;         // prefetch next k16
            if (kgn < 16) loadA8(af, A, rowM, kgn * 16, g, t);

#pragma unroll
            for (int jp2 = 0; jp2 < 2; ++jp2) {
                uint32_t off = sw128((uint32_t)((kk * 16 + krow) * 128 +
                                                (colW + jp2 * 16 + nadd) * 2));
                uint32_t bh[4], bl[4];
                ldsm4t(bh, bb + off);
                ldsm4t(bl, bb + PB_SLAB + off);
#pragma unroll
                for (int mt = 0; mt < 2; ++mt) {
                    float* c0 = acc + (mt * 4 + jp2 * 2) * 4;
                    float* c1 = acc + (mt * 4 + jp2 * 2 + 1) * 4;
                    mma16816(c0, ahi[mt], bh[0], bh[1]);
                    mma16816(c0, ahi[mt], bl[0], bl[1]);
                    mma16816(c0, alo[mt], bh[0], bh[1]);
                    mma16816(c1, ahi[mt], bh[2], bh[3]);
                    mma16816(c1, ahi[mt], bl[2], bl[3]);
                    mma16816(c1, alo[mt], bh[2], bh[3]);
                }
            }
        }
        __syncthreads();
    }
}

__device__ __forceinline__ void tc_store(
    const float* acc, float* __restrict__ C, int rowM, int colN, int lane)
{
    const int g = lane >> 2, t = lane & 3;
#pragma unroll
    for (int mt = 0; mt < 2; ++mt)
#pragma unroll
        for (int jp = 0; jp < 4; ++jp) {
            const float* c = acc + (mt * 4 + jp) * 4;
            int r = rowM + mt * 16 + g, col = colN + jp * 8 + 2 * t;
            *(float2*)&C[(size_t)r * NN + col] = make_float2(c[0], c[1]);
            *(float2*)&C[(size_t)(r + 8) * NN + col] = make_float2(c[2], c[3]);
        }
}

// ---------------------------------------------------------------------------
// Fused persistent precompute kernel. 256 CTAs x 128 threads.
// __launch_bounds__(128, 2): ptxas caps regs so 2 CTAs/SM always fit
// (smem 2x32KB = 64KB/SM also fits) -> all 256 CTAs co-resident on 148 SMs,
// so the global software barrier cannot deadlock.
// Phases: init | S-stage M=1,2,4,8 | TMP | Afinal.
// ---------------------------------------------------------------------------
__global__ void __launch_bounds__(128, 2) k_pre_fused(
    const float* __restrict__ W1, const float* __restrict__ U1,
    const float* __restrict__ W2, const float* __restrict__ U2,
    const float* __restrict__ Wo)
{
    extern __shared__ char smem[];
    const uint32_t sbu = s2u(smem);
    const int tid = threadIdx.x;
    const int w = tid >> 5, lane = tid & 31;
    const int g = lane >> 2, t = lane & 3;

    const int senseBase = g_sense;   // stable: no CTA can pass barrier 0 first
    int phase = 0;

    auto bar = [&]() {
        __syncthreads();
        if (tid == 0) {
            __threadfence();
            if (atomicAdd(&g_cnt, 1) == NCTA - 1) {
                atomicExch(&g_cnt, 0);
                __threadfence();
                atomicAdd((int*)&g_sense, 1);
            } else {
                int target = phase + 1;
                while (g_sense - senseBase < target) __nanosleep(64);
                __threadfence();
            }
        }
        ++phase;
        __syncthreads();
    };

    // ---- phase 0: init P1[1], P2[1], S[0] (32768 threads x 1 float2 each)
    {
        int idx = blockIdx.x * 128 + tid;
        ((float2*)g_P1[1])[idx] = ((const float2*)U1)[idx];
        ((float2*)g_P2[1])[idx] = ((const float2*)U2)[idx];
        ((float2*)g_S[0])[idx]  = ((const float2*)W2)[idx];
    }
    bar();

    // ---- S-doubling stages
    const int Ms[4]    = {1, 2, 4, 8};
    const int Njob[4]  = {3, 6, 12, 8};
#pragma unroll 1
    for (int s = 0; s < 4; ++s) {
        const int M = Ms[s];
        const int e_pow = min(M, 8 - M);
        for (int idx = blockIdx.x; idx < Njob[s] * 16; idx += NCTA) {
            const int job = idx >> 4, tile = idx & 15;
            const int rowBase = (tile >> 2) * 64, colBase = (tile & 3) * 64;
            const int rowM = rowBase + (w & 1) * 32;
            const int colW = (w >> 1) * 32;

            const float *A0, *B0, *A1 = nullptr, *B1 = nullptr;
            float* C;
            if (job < e_pow) {
                int j = job + 1;
                A0 = g_P1[M]; B0 = g_P1[j]; C = g_P1[M + j];
            } else if (job < 2 * e_pow) {
                int j = job - e_pow + 1;
                A0 = g_P2[M]; B0 = g_P2[j]; C = g_P2[M + j];
            } else {
                int m = M + (job - 2 * e_pow);
                A0 = g_S[M - 1]; B0 = g_P2[m - M + 1];
                A1 = g_P1[M];    B1 = g_S[m - M];
                C = g_S[m];
            }

            float acc[32] = {};
            tc_mm_pre(acc, A0, B0, smem, sbu, rowM, colBase, colW, lane, tid);
            if (A1) tc_mm_pre(acc, A1, B1, smem, sbu, rowM, colBase, colW, lane, tid);
            tc_store(acc, C, rowM, colBase + colW, lane);
        }
        bar();
    }

    // ---- TMP phase: TMP[m] = W1 @ S[m]   (16 jobs x 16 tiles = 256)
    for (int idx = blockIdx.x; idx < 256; idx += NCTA) {
        const int m = idx >> 4, tile = idx & 15;
        const int rowBase = (tile >> 2) * 64, colBase = (tile & 3) * 64;
        const int rowM = rowBase + (w & 1) * 32;
        const int colW = (w >> 1) * 32;
        float acc[32] = {};
        tc_mm_pre(acc, W1, g_S[m], smem, sbu, rowM, colBase, colW, lane, tid);
        tc_store(acc, g_TMP[m], rowM, colBase + colW, lane);
    }
    bar();

    // ---- Afinal phase: A_t = TMP[15-t] @ Wo, emit transposed bf16-split
    for (int idx = blockIdx.x; idx < 256; idx += NCTA) {
        const int tIdx = idx >> 4, tile = idx & 15;
        const int rowBase = (tile >> 2) * 64, colBase = (tile & 3) * 64;
        const int rowM = rowBase + (w & 1) * 32;
        const int colW = (w >> 1) * 32;

        float acc[32] = {};
        tc_mm_pre(acc, g_TMP[15 - tIdx], Wo, smem, sbu, rowM, colBase, colW,
                  lane, tid);

        float* cs = (float*)smem;   // reuse as [64][68] transpose buffer
#pragma unroll
        for (int mt = 0; mt < 2; ++mt)
#pragma unroll
            for (int jp = 0; jp < 4; ++jp) {
                const float* c = acc + (mt * 4 + jp) * 4;
                int lr = (w & 1) * 32 + mt * 16 + g;
                int lc = colW + jp * 8 + 2 * t;
                cs[lr * 68 + lc] = c[0];
                cs[lr * 68 + lc + 1] = c[1];
                cs[(lr + 8) * 68 + lc] = c[2];
                cs[(lr + 8) * 68 + lc + 1] = c[3];
            }
        __syncthreads();

        for (int j = tid; j < 64 * 16; j += 128) {
            int n = j >> 4, m4 = j & 15;
            int kg = tIdx * NN + rowBase + m4 * 4;
            __nv_bfloat16 h[4], l[4];
#pragma unroll
            for (int r = 0; r < 4; ++r) {
                float v = cs[(m4 * 4 + r) * 68 + n];
                h[r] = __float2bfloat16_rn(v);
                l[r] = __float2bfloat16_rn(v - __bfloat162float(h[r]));
            }
            *(uint64_t*)&g_Bhi[(size_t)(colBase + n) * KTOT + kg] = *(uint64_t*)h;
            *(uint64_t*)&g_Blo[(size_t)(colBase + n) * KTOT + kg] = *(uint64_t*)l;
        }
        __syncthreads();   // protect smem before any next tile
    }
}

// ---------------------------------------------------------------------------
// Main GEMM on mma.sync: out[8192,256] = X @ Acat. (validated R3/R6/R8)
// ---------------------------------------------------------------------------
#define BM 128
#define BN 128
#define BKC 64
#define NCHUNK (KTOT / BKC)
#define BUFB 32768
#define GEMM_SMEM (2 * BUFB)

__global__ void __launch_bounds__(256)
k_gemm_mma(const float* __restrict__ X, float* __restrict__ out)
{
    extern __shared__ char smem[];
    const uint32_t sb = s2u(smem);
    const int tid = threadIdx.x;
    const int w = tid >> 5, l = tid & 31;
    const int rowBase = blockIdx.x * BM;
    const int colBase = blockIdx.y * BN;

    auto loadB = [&](int c, int b) {
        const uint32_t dhi = sb + b * BUFB;
        const uint32_t dlo = dhi + 16384;
#pragma unroll
        for (int p = 0; p < 4; ++p) {
            int id = tid + p * 256;
            int n = id >> 3, cc = id & 7;
            uint32_t off = sw128((uint32_t)(n * 128 + cc * 16));
            size_t gidx = (size_t)(colBase + n) * KTOT + c * BKC + cc * 8;
            cp16(dhi + off, &g_Bhi[gidx]);
            cp16(dlo + off, &g_Blo[gidx]);
        }
    };

    loadB(0, 0);
    cp_commit();

    const float* p0 = X + (size_t)(rowBase + w * 16 + (l >> 2)) * KTOT + (l & 3) * 2;
    const float* p1 = p0 + (size_t)8 * KTOT;

    float2 aN0 = *(const float2*)(p0);
    float2 aN1 = *(const float2*)(p1);
    float2 aN2 = *(const float2*)(p0 + 8);
    float2 aN3 = *(const float2*)(p1 + 8);

    float acc[16][4];
#pragma unroll
    for (int j = 0; j < 16; ++j)
#pragma unroll
        for (int q = 0; q < 4; ++q) acc[j][q] = 0.f;

    const uint32_t tb0 = (uint32_t)((((l >> 4) * 8) + (l & 7)) * 128 + ((l >> 3) & 1) * 16);
    const uint32_t swx = (uint32_t)((l & 7) << 4);

    for (int c = 0; c < NCHUNK; ++c) {
        if (c + 1 < NCHUNK) loadB(c + 1, (c + 1) & 1);
        cp_commit();
        cp_wait1();
        __syncthreads();

        const uint32_t bhiB = sb + (c & 1) * BUFB;
        const uint32_t bloB = bhiB + 16384;

#pragma unroll
        for (int kk = 0; kk < 4; ++kk) {
            uint32_t ahi[4], alo[4];
            splitf2(aN0, ahi[0], alo[0]);
            splitf2(aN1, ahi[1], alo[1]);
            splitf2(aN2, ahi[2], alo[2]);
            splitf2(aN3, ahi[3], alo[3]);

            int kn = c * 4 + kk + 1;
            if (kn < KTOT / 16) {
                int kb = kn * 16;
                aN0 = *(const float2*)(p0 + kb);
                aN1 = *(const float2*)(p1 + kb);
                aN2 = *(const float2*)(p0 + kb + 8);
                aN3 = *(const float2*)(p1 + kb + 8);
            }

#pragma unroll
            for (int jp = 0; jp < 8; ++jp) {
                uint32_t aoff = ((tb0 + (uint32_t)(kk * 32) + (uint32_t)(jp * 2048)) ^ swx);
                uint32_t bh[4], bl[4];
                ldsm4(bh, bhiB + aoff);
                ldsm4(bl, bloB + aoff);
                mma16816(acc[2 * jp],     ahi, bh[0], bh[1]);
                mma16816(acc[2 * jp],     ahi, bl[0], bl[1]);
                mma16816(acc[2 * jp],     alo, bh[0], bh[1]);
                mma16816(acc[2 * jp + 1], ahi, bh[2], bh[3]);
                mma16816(acc[2 * jp + 1], ahi, bl[2], bl[3]);
                mma16816(acc[2 * jp + 1], alo, bh[2], bh[3]);
            }
        }
        __syncthreads();
    }

    const int r0 = rowBase + w * 16 + (l >> 2);
    const int nb = colBase + (l & 3) * 2;
#pragma unroll
    for (int j = 0; j < 16; ++j) {
        int n = nb + j * 8;
        *(float2*)&out[(size_t)r0 * NN + n] = make_float2(acc[j][0], acc[j][1]);
        *(float2*)&out[(size_t)(r0 + 8) * NN + n] = make_float2(acc[j][2], acc[j][3]);
    }
}

// ---------------------------------------------------------------------------
extern "C" void kernel_launch(void* const* d_in, const int* in_sizes, int n_in,
                              void* d_out, int out_size)
{
    const float* x  = (const float*)d_in[0];
    const float* W1 = (const float*)d_in[1];
    const float* U1 = (const float*)d_in[2];
    const float* W2 = (const float*)d_in[3];
    const float* U2 = (const float*)d_in[4];
    const float* Wo = (const float*)d_in[5];
    float* out = (float*)d_out;

    cudaFuncSetAttribute(k_pre_fused, cudaFuncAttributeMaxDynamicSharedMemorySize,
                         PRE_SMEM);
    cudaFuncSetAttribute(k_gemm_mma, cudaFuncAttributeMaxDynamicSharedMemorySize,
                         GEMM_SMEM);

    k_pre_fused<<<NCTA, 128, PRE_SMEM>>>(W1, U1, W2, U2, Wo);
    k_gemm_mma<<<dim3(BB / BM, NN / BN), 256, GEMM_SMEM>>>(x, out);
}

// round 10
// speedup vs baseline: 1.6113x; 1.0575x over previous
#include <cuda_runtime.h>
#include <cuda_bf16.h>
#include <cstdint>

// rnn_two: out = h2_last @ Wo for two stacked LINEAR SimpleRNNs.
// Linearity => out = sum_t x_t @ A_t with A_t = W1 @ S(15-t) @ Wo,
// S(m) = sum_{j=0..m} U1^j W2 U2^(m-j), via log-depth doubling.
// All matmuls on mma.sync bf16 hi/lo split (3 products, fp32 accum).
// Precompute: one persistent fused kernel. Main GEMM: BM128xBN64 tiles,
// 256 CTAs with 2-CTA/SM co-residency for latency hiding.

#define NN 256
#define TT 16
#define MSZ (NN * NN)
#define BB 8192
#define KTOT (TT * NN)   // 4096
#define NCTA 256         // persistent precompute grid

__device__ __align__(16) float g_P1[9][MSZ];
__device__ __align__(16) float g_P2[9][MSZ];
__device__ __align__(16) float g_S[TT][MSZ];
__device__ __align__(16) float g_TMP[TT][MSZ];
// Acat transposed + bf16-split: g_Bhi/lo[n][kglobal], kglobal = t*256 + j
__device__ __align__(16) __nv_bfloat16 g_Bhi[NN * KTOT];
__device__ __align__(16) __nv_bfloat16 g_Blo[NN * KTOT];

// global barrier state (replay-safe: cnt returns to 0, sense read relative)
__device__ int g_cnt;
__device__ volatile int g_sense;

// ---------------------------------------------------------------------------
// Common helpers
// ---------------------------------------------------------------------------
__device__ __forceinline__ uint32_t s2u(const void* p) {
    uint32_t a;
    asm("{ .reg .u64 t; cvta.to.shared.u64 t, %1; cvt.u32.u64 %0, t; }"
        : "=r"(a) : "l"(p));
    return a;
}
__device__ __forceinline__ uint32_t sw128(uint32_t b) {
    return b ^ ((b >> 3) & 0x70);
}
__device__ __forceinline__ void cp16(uint32_t dst, const void* src) {
    asm volatile("cp.async.cg.shared.global [%0], [%1], 16;"
                 :: "r"(dst), "l"(src));
}
__device__ __forceinline__ void cp_commit() {
    asm volatile("cp.async.commit_group;");
}
__device__ __forceinline__ void cp_wait1() {
    asm volatile("cp.async.wait_group 1;" ::: "memory");
}
__device__ __forceinline__ void ldsm4(uint32_t r[4], uint32_t addr) {
    asm volatile("ldmatrix.sync.aligned.m8n8.x4.shared.b16 {%0,%1,%2,%3}, [%4];"
                 : "=r"(r[0]), "=r"(r[1]), "=r"(r[2]), "=r"(r[3]) : "r"(addr));
}
__device__ __forceinline__ void ldsm4t(uint32_t r[4], uint32_t addr) {
    asm volatile("ldmatrix.sync.aligned.m8n8.x4.trans.shared.b16 {%0,%1,%2,%3}, [%4];"
                 : "=r"(r[0]), "=r"(r[1]), "=r"(r[2]), "=r"(r[3]) : "r"(addr));
}
__device__ __forceinline__ void mma16816(float c[4], const uint32_t a[4],
                                         uint32_t b0, uint32_t b1) {
    asm volatile(
        "mma.sync.aligned.m16n8k16.row.col.f32.bf16.bf16.f32 "
        "{%0,%1,%2,%3}, {%4,%5,%6,%7}, {%8,%9}, {%0,%1,%2,%3};"
        : "+f"(c[0]), "+f"(c[1]), "+f"(c[2]), "+f"(c[3])
        : "r"(a[0]), "r"(a[1]), "r"(a[2]), "r"(a[3]), "r"(b0), "r"(b1));
}
__device__ __forceinline__ void splitf2(float2 v, uint32_t& hi, uint32_t& lo) {
    __nv_bfloat162 h = __float22bfloat162_rn(v);
    float2 hf = __bfloat1622float2(h);
    __nv_bfloat162 L = __float22bfloat162_rn(make_float2(v.x - hf.x, v.y - hf.y));
    hi = *reinterpret_cast<uint32_t*>(&h);
    lo = *reinterpret_cast<uint32_t*>(&L);
}

// ---------------------------------------------------------------------------
// Precompute matmul core (validated R8/R9): 64x64 CTA tile, 128 threads.
// ---------------------------------------------------------------------------
#define KC 64
#define PB_SLAB 8192
#define PRE_BUF 16384
#define PRE_SMEM 32768

__device__ __forceinline__ void preB_ld(const float* __restrict__ B, int colBase,
                                        int c, int tid, float4 v[8]) {
#pragma unroll
    for (int p = 0; p < 8; ++p) {
        int id = tid + p * 128;
        int k = id >> 4, n4 = id & 15;
        v[p] = *(const float4*)&B[(size_t)(c * KC + k) * NN + colBase + n4 * 4];
    }
}
__device__ __forceinline__ void preB_st(char* buf, int tid, const float4 v[8]) {
#pragma unroll
    for (int p = 0; p < 8; ++p) {
        int id = tid + p * 128;
        int k = id >> 4, n4 = id & 15;
        uint32_t h0, l0, h1, l1;
        splitf2(make_float2(v[p].x, v[p].y), h0, l0);
        splitf2(make_float2(v[p].z, v[p].w), h1, l1);
        uint32_t off = sw128((uint32_t)(k * 128 + n4 * 8));
        *(uint2*)(buf + off) = make_uint2(h0, h1);
        *(uint2*)(buf + PB_SLAB + off) = make_uint2(l0, l1);
    }
}
__device__ __forceinline__ void loadA8(float2 af[8], const float* __restrict__ A,
                                       int rowM, int k0, int g, int t) {
#pragma unroll
    for (int mt = 0; mt < 2; ++mt) {
        const float* p = A + (size_t)(rowM + mt * 16 + g) * NN + k0 + 2 * t;
        af[mt * 4 + 0] = *(const float2*)p;
        af[mt * 4 + 1] = *(const float2*)(p + 8 * NN);
        af[mt * 4 + 2] = *(const float2*)(p + 8);
        af[mt * 4 + 3] = *(const float2*)(p + 8 * NN + 8);
    }
}

__device__ __forceinline__ void tc_mm_pre(
    float* acc,  // [2mt][4jp][4] = 32
    const float* __restrict__ A, const float* __restrict__ B,
    char* smem, uint32_t sbu, int rowM, int colBase, int colW, int lane, int tid)
{
    const int g = lane >> 2, t = lane & 3;
    const int krow = ((lane >> 3) & 1) * 8 + (lane & 7);
    const int nadd = ((lane >> 4) & 1) * 8;

    float4 breg[8];
    preB_ld(B, colBase, 0, tid, breg);
    float2 af[8];
    loadA8(af, A, rowM, 0, g, t);

    for (int c = 0; c < NN / KC; ++c) {
        char* buf = smem + (c & 1) * PRE_BUF;
        preB_st(buf, tid, breg);
        __syncthreads();
        if (c + 1 < NN / KC) preB_ld(B, colBase, c + 1, tid, breg);

        const uint32_t bb = sbu + (uint32_t)((c & 1) * PRE_BUF);
#pragma unroll
        for (int kk = 0; kk < 4; ++kk) {
            uint32_t ahi[2][4], alo[2][4];
#pragma unroll
            for (int q = 0; q < 8; ++q)
                splitf2(af[q], ahi[q >> 2][q & 3], alo[q >> 2][q & 3]);

            int kgn = c * 4 + kk + 1;
            if (kgn < 16) loadA8(af, A, rowM, kgn * 16, g, t);

#pragma unroll
            for (int jp2 = 0; jp2 < 2; ++jp2) {
                uint32_t off = sw128((uint32_t)((kk * 16 + krow) * 128 +
                                                (colW + jp2 * 16 + nadd) * 2));
                uint32_t bh[4], bl[4];
                ldsm4t(bh, bb + off);
                ldsm4t(bl, bb + PB_SLAB + off);
#pragma unroll
                for (int mt = 0; mt < 2; ++mt) {
                    float* c0 = acc + (mt * 4 + jp2 * 2) * 4;
                    float* c1 = acc + (mt * 4 + jp2 * 2 + 1) * 4;
                    mma16816(c0, ahi[mt], bh[0], bh[1]);
                    mma16816(c0, ahi[mt], bl[0], bl[1]);
                    mma16816(c0, alo[mt], bh[0], bh[1]);
                    mma16816(c1, ahi[mt], bh[2], bh[3]);
                    mma16816(c1, ahi[mt], bl[2], bl[3]);
                    mma16816(c1, alo[mt], bh[2], bh[3]);
                }
            }
        }
        __syncthreads();
    }
}

__device__ __forceinline__ void tc_store(
    const float* acc, float* __restrict__ C, int rowM, int colN, int lane)
{
    const int g = lane >> 2, t = lane & 3;
#pragma unroll
    for (int mt = 0; mt < 2; ++mt)
#pragma unroll
        for (int jp = 0; jp < 4; ++jp) {
            const float* c = acc + (mt * 4 + jp) * 4;
            int r = rowM + mt * 16 + g, col = colN + jp * 8 + 2 * t;
            *(float2*)&C[(size_t)r * NN + col] = make_float2(c[0], c[1]);
            *(float2*)&C[(size_t)(r + 8) * NN + col] = make_float2(c[2], c[3]);
        }
}

// ---------------------------------------------------------------------------
// Fused persistent precompute kernel (validated R9).
// ---------------------------------------------------------------------------
__global__ void __launch_bounds__(128, 2) k_pre_fused(
    const float* __restrict__ W1, const float* __restrict__ U1,
    const float* __restrict__ W2, const float* __restrict__ U2,
    const float* __restrict__ Wo)
{
    extern __shared__ char smem[];
    const uint32_t sbu = s2u(smem);
    const int tid = threadIdx.x;
    const int w = tid >> 5, lane = tid & 31;
    const int g = lane >> 2, t = lane & 3;

    const int senseBase = g_sense;
    int phase = 0;

    auto bar = [&]() {
        __syncthreads();
        if (tid == 0) {
            __threadfence();
            if (atomicAdd(&g_cnt, 1) == NCTA - 1) {
                atomicExch(&g_cnt, 0);
                __threadfence();
                atomicAdd((int*)&g_sense, 1);
            } else {
                int target = phase + 1;
                while (g_sense - senseBase < target) __nanosleep(64);
                __threadfence();
            }
        }
        ++phase;
        __syncthreads();
    };

    {
        int idx = blockIdx.x * 128 + tid;
        ((float2*)g_P1[1])[idx] = ((const float2*)U1)[idx];
        ((float2*)g_P2[1])[idx] = ((const float2*)U2)[idx];
        ((float2*)g_S[0])[idx]  = ((const float2*)W2)[idx];
    }
    bar();

    const int Ms[4]    = {1, 2, 4, 8};
    const int Njob[4]  = {3, 6, 12, 8};
#pragma unroll 1
    for (int s = 0; s < 4; ++s) {
        const int M = Ms[s];
        const int e_pow = min(M, 8 - M);
        for (int idx = blockIdx.x; idx < Njob[s] * 16; idx += NCTA) {
            const int job = idx >> 4, tile = idx & 15;
            const int rowBase = (tile >> 2) * 64, colBase = (tile & 3) * 64;
            const int rowM = rowBase + (w & 1) * 32;
            const int colW = (w >> 1) * 32;

            const float *A0, *B0, *A1 = nullptr, *B1 = nullptr;
            float* C;
            if (job < e_pow) {
                int j = job + 1;
                A0 = g_P1[M]; B0 = g_P1[j]; C = g_P1[M + j];
            } else if (job < 2 * e_pow) {
                int j = job - e_pow + 1;
                A0 = g_P2[M]; B0 = g_P2[j]; C = g_P2[M + j];
            } else {
                int m = M + (job - 2 * e_pow);
                A0 = g_S[M - 1]; B0 = g_P2[m - M + 1];
                A1 = g_P1[M];    B1 = g_S[m - M];
                C = g_S[m];
            }

            float acc[32] = {};
            tc_mm_pre(acc, A0, B0, smem, sbu, rowM, colBase, colW, lane, tid);
            if (A1) tc_mm_pre(acc, A1, B1, smem, sbu, rowM, colBase, colW, lane, tid);
            tc_store(acc, C, rowM, colBase + colW, lane);
        }
        bar();
    }

    for (int idx = blockIdx.x; idx < 256; idx += NCTA) {
        const int m = idx >> 4, tile = idx & 15;
        const int rowBase = (tile >> 2) * 64, colBase = (tile & 3) * 64;
        const int rowM = rowBase + (w & 1) * 32;
        const int colW = (w >> 1) * 32;
        float acc[32] = {};
        tc_mm_pre(acc, W1, g_S[m], smem, sbu, rowM, colBase, colW, lane, tid);
        tc_store(acc, g_TMP[m], rowM, colBase + colW, lane);
    }
    bar();

    for (int idx = blockIdx.x; idx < 256; idx += NCTA) {
        const int tIdx = idx >> 4, tile = idx & 15;
        const int rowBase = (tile >> 2) * 64, colBase = (tile & 3) * 64;
        const int rowM = rowBase + (w & 1) * 32;
        const int colW = (w >> 1) * 32;

        float acc[32] = {};
        tc_mm_pre(acc, g_TMP[15 - tIdx], Wo, smem, sbu, rowM, colBase, colW,
                  lane, tid);

        float* cs = (float*)smem;   // reuse as [64][68] transpose buffer
#pragma unroll
        for (int mt = 0; mt < 2; ++mt)
#pragma unroll
            for (int jp = 0; jp < 4; ++jp) {
                const float* c = acc + (mt * 4 + jp) * 4;
                int lr = (w & 1) * 32 + mt * 16 + g;
                int lc = colW + jp * 8 + 2 * t;
                cs[lr * 68 + lc] = c[0];
                cs[lr * 68 + lc + 1] = c[1];
                cs[(lr + 8) * 68 + lc] = c[2];
                cs[(lr + 8) * 68 + lc + 1] = c[3];
            }
        __syncthreads();

        for (int j = tid; j < 64 * 16; j += 128) {
            int n = j >> 4, m4 = j & 15;
            int kg = tIdx * NN + rowBase + m4 * 4;
            __nv_bfloat16 h[4], l[4];
#pragma unroll
            for (int r = 0; r < 4; ++r) {
                float v = cs[(m4 * 4 + r) * 68 + n];
                h[r] = __float2bfloat16_rn(v);
                l[r] = __float2bfloat16_rn(v - __bfloat162float(h[r]));
            }
            *(uint64_t*)&g_Bhi[(size_t)(colBase + n) * KTOT + kg] = *(uint64_t*)h;
            *(uint64_t*)&g_Blo[(size_t)(colBase + n) * KTOT + kg] = *(uint64_t*)l;
        }
        __syncthreads();
    }
}

// ---------------------------------------------------------------------------
// Main GEMM: out[8192,256] = X @ Acat.  BM=128, BN=64, 256 threads,
// warp = 16m x 64n (acc[8][4]). Grid (64,4)=256 CTAs; launch_bounds(256,2)
// guarantees 2 CTAs/SM (occ 25%) for latency hiding.
// ---------------------------------------------------------------------------
#define BM 128
#define BN 64
#define BKC 64
#define NCHUNK (KTOT / BKC)
#define BUFB 16384              // bhi 8K + blo 8K
#define GEMM_SMEM (2 * BUFB)    // 32 KB

__global__ void __launch_bounds__(256, 2)
k_gemm_mma(const float* __restrict__ X, float* __restrict__ out)
{
    extern __shared__ char smem[];
    const uint32_t sb = s2u(smem);
    const int tid = threadIdx.x;
    const int w = tid >> 5, l = tid & 31;
    const int rowBase = blockIdx.x * BM;
    const int colBase = blockIdx.y * BN;

    // B chunk loader: 64n x 64k hi+lo -> swizzled smem (2 cp16/thread each)
    auto loadB = [&](int c, int b) {
        const uint32_t dhi = sb + b * BUFB;
        const uint32_t dlo = dhi + 8192;
#pragma unroll
        for (int p = 0; p < 2; ++p) {
            int id = tid + p * 256;           // 512 chunks of 16B
            int n = id >> 3, cc = id & 7;
            uint32_t off = sw128((uint32_t)(n * 128 + cc * 16));
            size_t gidx = (size_t)(colBase + n) * KTOT + c * BKC + cc * 8;
            cp16(dhi + off, &g_Bhi[gidx]);
            cp16(dlo + off, &g_Blo[gidx]);
        }
    };

    loadB(0, 0);
    cp_commit();

    const float* p0 = X + (size_t)(rowBase + w * 16 + (l >> 2)) * KTOT + (l & 3) * 2;
    const float* p1 = p0 + (size_t)8 * KTOT;

    float2 aN0 = *(const float2*)(p0);
    float2 aN1 = *(const float2*)(p1);
    float2 aN2 = *(const float2*)(p0 + 8);
    float2 aN3 = *(const float2*)(p1 + 8);

    float acc[8][4];
#pragma unroll
    for (int j = 0; j < 8; ++j)
#pragma unroll
        for (int q = 0; q < 4; ++q) acc[j][q] = 0.f;

    const uint32_t tb0 = (uint32_t)((((l >> 4) * 8) + (l & 7)) * 128 + ((l >> 3) & 1) * 16);
    const uint32_t swx = (uint32_t)((l & 7) << 4);

    for (int c = 0; c < NCHUNK; ++c) {
        if (c + 1 < NCHUNK) loadB(c + 1, (c + 1) & 1);
        cp_commit();
        cp_wait1();
        __syncthreads();

        const uint32_t bhiB = sb + (c & 1) * BUFB;
        const uint32_t bloB = bhiB + 8192;

#pragma unroll
        for (int kk = 0; kk < 4; ++kk) {
            uint32_t ahi[4], alo[4];
            splitf2(aN0, ahi[0], alo[0]);
            splitf2(aN1, ahi[1], alo[1]);
            splitf2(aN2, ahi[2], alo[2]);
            splitf2(aN3, ahi[3], alo[3]);

            int kn = c * 4 + kk + 1;
            if (kn < KTOT / 16) {
                int kb = kn * 16;
                aN0 = *(const float2*)(p0 + kb);
                aN1 = *(const float2*)(p1 + kb);
                aN2 = *(const float2*)(p0 + kb + 8);
                aN3 = *(const float2*)(p1 + kb + 8);
            }

#pragma unroll
            for (int jp = 0; jp < 4; ++jp) {   // 4 n16 groups = 64n
                uint32_t aoff = ((tb0 + (uint32_t)(kk * 32) + (uint32_t)(jp * 2048)) ^ swx);
                uint32_t bh[4], bl[4];
                ldsm4(bh, bhiB + aoff);
                ldsm4(bl, bloB + aoff);
                mma16816(acc[2 * jp],     ahi, bh[0], bh[1]);
                mma16816(acc[2 * jp],     ahi, bl[0], bl[1]);
                mma16816(acc[2 * jp],     alo, bh[0], bh[1]);
                mma16816(acc[2 * jp + 1], ahi, bh[2], bh[3]);
                mma16816(acc[2 * jp + 1], ahi, bl[2], bl[3]);
                mma16816(acc[2 * jp + 1], alo, bh[2], bh[3]);
            }
        }
        __syncthreads();
    }

    const int r0 = rowBase + w * 16 + (l >> 2);
    const int nb = colBase + (l & 3) * 2;
#pragma unroll
    for (int j = 0; j < 8; ++j) {
        int n = nb + j * 8;
        *(float2*)&out[(size_t)r0 * NN + n] = make_float2(acc[j][0], acc[j][1]);
        *(float2*)&out[(size_t)(r0 + 8) * NN + n] = make_float2(acc[j][2], acc[j][3]);
    }
}

// ---------------------------------------------------------------------------
extern "C" void kernel_launch(void* const* d_in, const int* in_sizes, int n_in,
                              void* d_out, int out_size)
{
    const float* x  = (const float*)d_in[0];
    const float* W1 = (const float*)d_in[1];
    const float* U1 = (const float*)d_in[2];
    const float* W2 = (const float*)d_in[3];
    const float* U2 = (const float*)d_in[4];
    const float* Wo = (const float*)d_in[5];
    float* out = (float*)d_out;

    cudaFuncSetAttribute(k_pre_fused, cudaFuncAttributeMaxDynamicSharedMemorySize,
                         PRE_SMEM);
    cudaFuncSetAttribute(k_gemm_mma, cudaFuncAttributeMaxDynamicSharedMemorySize,
                         GEMM_SMEM);

    k_pre_fused<<<NCTA, 128, PRE_SMEM>>>(W1, U1, W2, U2, Wo);
    k_gemm_mma<<<dim3(BB / BM, NN / BN), 256, GEMM_SMEM>>>(x, out);
}